// round 10
// baseline (speedup 1.0000x reference)
#include <cuda_runtime.h>
#include <cstdint>

#define MAX_SAMPLES 512
#define THREADS 1024
#define PPT 32                    // contiguous points per thread
#define WIN (THREADS * PPT)       // 32768-point window (fill point +10.7 sigma)

// Match XLA's non-contracted, left-associated ((x*x)+(y*y))+(z*z).
__device__ __forceinline__ int octant_of(float x, float y, float z) {
    float r2 = __fadd_rn(__fadd_rn(__fmul_rn(x, x), __fmul_rn(y, y)), __fmul_rn(z, z));
    if (!(r2 <= 1.0f)) return -1;
    return ((x >= 0.0f) ? 4 : 0) | ((y >= 0.0f) ? 2 : 0) | ((z >= 0.0f) ? 1 : 0);
}

// packed 16-bit-field helpers: h[idx] holds octants (2*idx, 2*idx+1)
__device__ __forceinline__ unsigned sel4(unsigned a, unsigned b, unsigned c,
                                         unsigned d, int idx) {
    unsigned r = a;
    r = (idx == 1) ? b : r;
    r = (idx == 2) ? c : r;
    r = (idx == 3) ? d : r;
    return r;
}

// One block per batch. Thread t owns contiguous points [win + t*32, +32), so
// thread order == index order: local hist -> one packed block scan -> each
// thread writes its points at base[oct] + local_rank (recorded during hist).
__global__ __launch_bounds__(THREADS, 1)
void octant_query_fused(const float* __restrict__ pcs, float* __restrict__ out, int N) {
    const int b    = blockIdx.x;
    const int tid  = threadIdx.x;
    const int lane = tid & 31;
    const int w    = tid >> 5;

    const float* __restrict__ xs = pcs + (size_t)b * 3 * N;
    const float* __restrict__ ys = xs + N;
    const float* __restrict__ zs = ys + N;
    float* __restrict__ out_b = out + (size_t)b * (8 * MAX_SAMPLES);

    __shared__ unsigned sm_ws[32][4];   // warp sums -> overwritten w/ warp offsets
    __shared__ int sh_gbase[8];         // running global base per octant
    __shared__ int sh_tot[8];           // this window's totals

    if (tid < 8) sh_gbase[tid] = 0;
    __syncthreads();

    for (int win = 0; win < N; win += WIN) {
        // ---- load, classify, local hist (+ per-point local rank) ----
        unsigned h0 = 0, h1 = 0, h2 = 0, h3 = 0;   // 8 x 16-bit counters
        unsigned vmask = 0;                        // valid (in-ball) bits
        unsigned pk[PPT / 4];                      // byte/pt: o<<5 | local_rank

        const int i0 = win + tid * PPT;
#pragma unroll
        for (int g = 0; g < PPT / 4; g++) {
            const int i = i0 + g * 4;
            float px[4], py[4], pz[4];
            if (i + 3 < N) {
                const float4 vx = *reinterpret_cast<const float4*>(xs + i);
                const float4 vy = *reinterpret_cast<const float4*>(ys + i);
                const float4 vz = *reinterpret_cast<const float4*>(zs + i);
                px[0] = vx.x; px[1] = vx.y; px[2] = vx.z; px[3] = vx.w;
                py[0] = vy.x; py[1] = vy.y; py[2] = vy.z; py[3] = vy.w;
                pz[0] = vz.x; pz[1] = vz.y; pz[2] = vz.z; pz[3] = vz.w;
            } else {
#pragma unroll
                for (int j = 0; j < 4; j++) {
                    const int ii = i + j;
                    const bool ok = (ii < N);
                    px[j] = ok ? xs[ii] : 2.0f;   // outside ball
                    py[j] = ok ? ys[ii] : 2.0f;
                    pz[j] = ok ? zs[ii] : 2.0f;
                }
            }
            unsigned word = 0;
#pragma unroll
            for (int j = 0; j < 4; j++) {
                const int o = octant_of(px[j], py[j], pz[j]);
                if (o >= 0) {
                    vmask |= 1u << (g * 4 + j);
                    const int idx = o >> 1;
                    const int sh  = (o & 1) * 16;
                    const unsigned cur = sel4(h0, h1, h2, h3, idx);
                    const unsigned lr  = (cur >> sh) & 0xFFFFu;   // local rank
                    word |= (((unsigned)o << 5) | lr) << (8 * j);
                    const unsigned inc = 1u << sh;
                    h0 += (idx == 0) ? inc : 0u;
                    h1 += (idx == 1) ? inc : 0u;
                    h2 += (idx == 2) ? inc : 0u;
                    h3 += (idx == 3) ? inc : 0u;
                }
            }
            pk[g] = word;
        }

        // ---- block-wide packed exclusive scan (thread order) ----
        unsigned s0 = h0, s1 = h1, s2 = h2, s3 = h3;   // inclusive within warp
#pragma unroll
        for (int d = 1; d < 32; d <<= 1) {
            unsigned t0 = __shfl_up_sync(0xFFFFFFFFu, s0, d);
            unsigned t1 = __shfl_up_sync(0xFFFFFFFFu, s1, d);
            unsigned t2 = __shfl_up_sync(0xFFFFFFFFu, s2, d);
            unsigned t3 = __shfl_up_sync(0xFFFFFFFFu, s3, d);
            if (lane >= d) { s0 += t0; s1 += t1; s2 += t2; s3 += t3; }
        }
        if (lane == 31) {
            sm_ws[w][0] = s0; sm_ws[w][1] = s1; sm_ws[w][2] = s2; sm_ws[w][3] = s3;
        }
        __syncthreads();                                       // (A)

        if (w == 0) {
            unsigned t0 = sm_ws[lane][0], t1 = sm_ws[lane][1];
            unsigned t2 = sm_ws[lane][2], t3 = sm_ws[lane][3];
            const unsigned o0 = t0, o1 = t1, o2 = t2, o3 = t3;  // own warp sums
#pragma unroll
            for (int d = 1; d < 32; d <<= 1) {
                unsigned u0 = __shfl_up_sync(0xFFFFFFFFu, t0, d);
                unsigned u1 = __shfl_up_sync(0xFFFFFFFFu, t1, d);
                unsigned u2 = __shfl_up_sync(0xFFFFFFFFu, t2, d);
                unsigned u3 = __shfl_up_sync(0xFFFFFFFFu, t3, d);
                if (lane >= d) { t0 += u0; t1 += u1; t2 += u2; t3 += u3; }
            }
            sm_ws[lane][0] = t0 - o0;   // exclusive warp offsets
            sm_ws[lane][1] = t1 - o1;
            sm_ws[lane][2] = t2 - o2;
            sm_ws[lane][3] = t3 - o3;
            if (lane == 31) {           // window totals (inclusive at last warp)
                sh_tot[0] = (int)(t0 & 0xFFFFu); sh_tot[1] = (int)(t0 >> 16);
                sh_tot[2] = (int)(t1 & 0xFFFFu); sh_tot[3] = (int)(t1 >> 16);
                sh_tot[4] = (int)(t2 & 0xFFFFu); sh_tot[5] = (int)(t2 >> 16);
                sh_tot[6] = (int)(t3 & 0xFFFFu); sh_tot[7] = (int)(t3 >> 16);
            }
        }
        __syncthreads();                                       // (B)

        // thread-exclusive packed prefix
        const unsigned e0 = s0 - h0 + sm_ws[w][0];
        const unsigned e1 = s1 - h1 + sm_ws[w][1];
        const unsigned e2 = s2 - h2 + sm_ws[w][2];
        const unsigned e3 = s3 - h3 + sm_ws[w][3];

        int base[8];
        base[0] = sh_gbase[0] + (int)(e0 & 0xFFFFu);
        base[1] = sh_gbase[1] + (int)(e0 >> 16);
        base[2] = sh_gbase[2] + (int)(e1 & 0xFFFFu);
        base[3] = sh_gbase[3] + (int)(e1 >> 16);
        base[4] = sh_gbase[4] + (int)(e2 & 0xFFFFu);
        base[5] = sh_gbase[5] + (int)(e2 >> 16);
        base[6] = sh_gbase[6] + (int)(e3 & 0xFFFFu);
        base[7] = sh_gbase[7] + (int)(e3 >> 16);
        __syncthreads();                                       // (C) gbase read done

        if (tid < 8) sh_gbase[tid] += sh_tot[tid];

        // ---- independent per-point writes (no serial dependency) ----
        if (vmask) {
#pragma unroll
            for (int g = 0; g < PPT / 4; g++) {
                const unsigned word = pk[g];
#pragma unroll
                for (int j = 0; j < 4; j++) {
                    if (vmask & (1u << (g * 4 + j))) {
                        const int o  = (int)((word >> (8 * j + 5)) & 7u);
                        const int lr = (int)((word >> (8 * j)) & 31u);
                        const int r  = base[o] + lr;
                        if (r < MAX_SAMPLES)
                            out_b[(o << 9) + r] = (float)(i0 + g * 4 + j);
                    }
                }
            }
        }
        __syncthreads();                                       // (D)

        bool full = true;
#pragma unroll
        for (int q = 0; q < 8; q++) full = full && (sh_gbase[q] >= MAX_SAMPLES);
        if (full) break;
    }

    // ---- fill unwritten tail slots with DEFAULT (-1) ----
#pragma unroll
    for (int j = 0; j < (8 * MAX_SAMPLES) / THREADS; j++) {
        const int s = j * THREADS + tid;
        const int q = s >> 9;
        const int r = s & (MAX_SAMPLES - 1);
        if (r >= sh_gbase[q]) out_b[s] = -1.0f;
    }
}

extern "C" void kernel_launch(void* const* d_in, const int* in_sizes, int n_in,
                              void* d_out, int out_size) {
    const float* pcs = (const float*)d_in[0];
    float* out = (float*)d_out;

    int B = out_size / (8 * MAX_SAMPLES);   // 16
    if (B < 1) B = 1;
    if (B > 64) B = 64;
    int N = in_sizes[0] / (3 * B);          // 200000

    octant_query_fused<<<B, THREADS>>>(pcs, out, N);
}